// round 7
// baseline (speedup 1.0000x reference)
#include <cuda_runtime.h>

#define DIM   256     // DIM_IN
#define BATCH 1024    // B
#define NI    32640   // C(256,2)

#define TT     32     // i/j tile size (8 tiles of 32)
#define ROWS   64     // batch rows per block
#define NPAIR  36     // unordered tile pairs
#define XP     36     // x tile pitch in floats (144B rows: 16B-aligned, bank stride 8)

__constant__ unsigned char cTI[NPAIR] = {0,0,0,0,0,0,0,0, 1,1,1,1,1,1,1, 2,2,2,2,2,2,
                                         3,3,3,3,3, 4,4,4,4, 5,5,5, 6,6, 7};
__constant__ unsigned char cTJ[NPAIR] = {0,1,2,3,4,5,6,7, 1,2,3,4,5,6,7, 2,3,4,5,6,7,
                                         3,4,5,6,7, 4,5,6,7, 5,6,7, 6,7, 7};

__global__ void zero_out_kernel(float* __restrict__ out) {
    out[threadIdx.x] = 0.0f;
}

// Packed f32x2 FMA
__device__ __forceinline__ float2 fma2(float2 a, float2 b, float2 c) {
    float2 d;
    asm("fma.rn.f32x2 %0, %1, %2, %3;"
        : "=l"(*reinterpret_cast<unsigned long long*>(&d))
        : "l"(*reinterpret_cast<const unsigned long long*>(&a)),
          "l"(*reinterpret_cast<const unsigned long long*>(&b)),
          "l"(*reinterpret_cast<const unsigned long long*>(&c)));
    return d;
}

// 16B global->shared async copy (LDGSTS): no dst register, no dependency chain.
__device__ __forceinline__ void cp_async16(unsigned smem_addr, const void* gptr) {
    asm volatile("cp.async.ca.shared.global [%0], [%1], 16;"
                 :: "r"(smem_addr), "l"(__cvta_generic_to_global(gptr)) : "memory");
}

// out[b] = sum_{i<j} (w0+w1)*w0*w1 * x[b,i]*x[b,j]
// Block = one unordered (i-tile, j-tile) pair x 64 rows.
// Prologue: x tiles via cp.async (row-major, no transpose); A built from 8
// batched LDGs overlapped with the cp.async flight. One barrier total.
__global__ void __launch_bounds__(256, 4)
quad_kernel(const float* __restrict__ x, const float* __restrict__ w,
            float* __restrict__ out) {
    __shared__ __align__(16) float As [TT * TT];     // 4KB
    __shared__ __align__(16) float xIs[ROWS * XP];   // [row r][col i], 9.2KB
    __shared__ __align__(16) float xJs[ROWS * XP];   // [row r][col j], 9.2KB

    const int t     = threadIdx.x;
    const int pair  = blockIdx.x;
    const int ibase = cTI[pair] * TT;
    const int jbase = cTJ[pair] * TT;
    const int rbase = blockIdx.y * ROWS;

    const unsigned sI = (unsigned)__cvta_generic_to_shared(xIs);
    const unsigned sJ = (unsigned)__cvta_generic_to_shared(xJs);

    // ---- x tiles via cp.async: 512 16B-chunks per tile, 2 per thread per tile.
    // chunk c: row r = c>>3, 16B-piece cc = c&7. Warp covers 4 rows x 128B: coalesced.
#pragma unroll
    for (int s = 0; s < 2; ++s) {
        const int c  = s * 256 + t;
        const int r  = c >> 3, cc = c & 7;
        const long rowoff = (long)(rbase + r) * DIM;
        cp_async16(sI + (r * XP + cc * 4) * 4, x + rowoff + ibase + cc * 4);
        cp_async16(sJ + (r * XP + cc * 4) * 4, x + rowoff + jbase + cc * 4);
    }
    asm volatile("cp.async.commit_group;" ::: "memory");

    // ---- A tile: 4 cells/thread. Loads first (batch -> MLP 8), then compute+STS.
    float w0v[4], w1v[4];
    bool  val[4];
#pragma unroll
    for (int s = 0; s < 4; ++s) {
        const int idx = s * 256 + t;
        const int gi = ibase + (idx >> 5);
        const int gj = jbase + (idx & 31);
        val[s] = (gj > gi);
        const int k = val[s] ? (gi * 255 - (gi * (gi - 1)) / 2 + (gj - gi - 1)) : 0;
        w0v[s] = __ldg(&w[k]);
        w1v[s] = __ldg(&w[NI + k]);
    }
#pragma unroll
    for (int s = 0; s < 4; ++s) {
        const int idx = s * 256 + t;
        As[idx] = val[s] ? (w0v[s] + w1v[s]) * w0v[s] * w1v[s] : 0.0f;
    }

    asm volatile("cp.async.wait_group 0;" ::: "memory");
    __syncthreads();   // covers As stores + all threads' cp.async data

    // ---- Mainloop: thread tile = 2 rows x 4 j (lanes = j-pairs).
    const int jg = t & 7;             // 8 j-groups x 4 j = 32 j
    const int j0 = jg * 4;
    const int r0 = (t >> 3) * 2;      // 32 row-groups x 2 rows = 64 rows

    float2 a00 = {0.f,0.f}, a01 = {0.f,0.f}, a10 = {0.f,0.f}, a11 = {0.f,0.f};

#pragma unroll
    for (int i = 0; i < TT; ++i) {
        const float xv0 = xIs[ r0      * XP + i];   // broadcast LDS (4 addrs/warp, banks 8 apart)
        const float xv1 = xIs[(r0 + 1) * XP + i];
        const float4 av = *reinterpret_cast<const float4*>(&As[i * TT + j0]);
        const float2 A01 = make_float2(av.x, av.y);
        const float2 A23 = make_float2(av.z, av.w);
        a00 = fma2(make_float2(xv0, xv0), A01, a00);
        a01 = fma2(make_float2(xv0, xv0), A23, a01);
        a10 = fma2(make_float2(xv1, xv1), A01, a10);
        a11 = fma2(make_float2(xv1, xv1), A23, a11);
    }

    // ---- Epilogue: dot with x_J, shuffle-reduce the 8 j-groups.
    const float4 xj0 = *reinterpret_cast<const float4*>(&xJs[ r0      * XP + j0]);
    const float4 xj1 = *reinterpret_cast<const float4*>(&xJs[(r0 + 1) * XP + j0]);
    float2 s0 = fma2(a00, make_float2(xj0.x, xj0.y),
                fma2(a01, make_float2(xj0.z, xj0.w), make_float2(0.f, 0.f)));
    float2 s1 = fma2(a10, make_float2(xj1.x, xj1.y),
                fma2(a11, make_float2(xj1.z, xj1.w), make_float2(0.f, 0.f)));
    float v0 = s0.x + s0.y;
    float v1 = s1.x + s1.y;

#pragma unroll
    for (int m = 4; m > 0; m >>= 1) {
        v0 += __shfl_xor_sync(0xffffffffu, v0, m, 32);
        v1 += __shfl_xor_sync(0xffffffffu, v1, m, 32);
    }
    if (jg == 0) {
        atomicAdd(&out[rbase + r0],     v0);
        atomicAdd(&out[rbase + r0 + 1], v1);
    }
}

extern "C" void kernel_launch(void* const* d_in, const int* in_sizes, int n_in,
                              void* d_out, int out_size) {
    const float* x = (const float*)d_in[0];
    const float* w = (const float*)d_in[1];
    float* out = (float*)d_out;

    zero_out_kernel<<<1, BATCH>>>(out);
    quad_kernel<<<dim3(NPAIR, BATCH / ROWS), 256>>>(x, w, out);  // 576 blocks, ~4/SM
}